// round 4
// baseline (speedup 1.0000x reference)
#include <cuda_runtime.h>
#include <cuda_bf16.h>
#include <math.h>

// Problem constants
#define BB 64
#define SS 256
#define HH 1024
#define EE 512
#define GG 4096   // 4*H

// -------- scratch (device globals: sanctioned, no allocations) --------
__device__ float g_P0[(size_t)SS * BB * GG];  // precomputed input-side gates, 256 MB
__device__ float g_sp[BB * GG];               // static-part gates (time-invariant)
__device__ float g_b1[GG];                    // b_ih_l1 + b_hh_l1
__device__ float g_h0[2][BB * HH];            // double-buffered recurrent h (layer 0)
__device__ float g_h1[2][BB * HH];            // double-buffered recurrent h (layer 1)
__device__ float g_c0[BB * HH];               // cell states (owner-only access)
__device__ float g_c1[BB * HH];

// -------- packed fp32x2 FMA helpers --------
typedef unsigned long long u64t;

__device__ __forceinline__ void fma2(u64t& c, u64t a, u64t b) {
    asm("fma.rn.f32x2 %0, %1, %2, %0;" : "+l"(c) : "l"(a), "l"(b));
}
__device__ __forceinline__ float hsum2(u64t v) {
    return __uint_as_float((unsigned)(v & 0xffffffffu)) +
           __uint_as_float((unsigned)(v >> 32));
}
__device__ __forceinline__ float sigf(float x) { return 1.0f / (1.0f + expf(-x)); }

// =====================================================================
// k_init: copy initial states, fold layer-1 biases
// =====================================================================
__global__ void k_init(const float* __restrict__ enc_h, const float* __restrict__ enc_c,
                       const float* __restrict__ b_ih1, const float* __restrict__ b_hh1) {
    int i = blockIdx.x * blockDim.x + threadIdx.x;
    const int n = BB * HH;
    if (i < n) {
        g_h0[0][i] = enc_h[i];
        g_c0[i]    = enc_c[i];
        g_h1[0][i] = enc_h[n + i];
        g_c1[i]    = enc_c[n + i];
    }
    if (i < GG) g_b1[i] = b_ih1[i] + b_hh1[i];
}

// =====================================================================
// k_static: g_sp[b][g] = static[b] @ W_ih_l0[:,512:1536].T + b_ih0 + b_hh0
// static[b] = concat(encoder_outs[b,127,:], embed[src_lang[b]])
// grid (GG/256, BB/8), 256 threads. Each thread: one g, 8 batches.
// =====================================================================
__global__ void __launch_bounds__(256) k_static(
    const float* __restrict__ enc_outs, const int* __restrict__ src_lang,
    const float* __restrict__ embed, const float* __restrict__ W0,
    const float* __restrict__ b_ih0, const float* __restrict__ b_hh0) {
    __shared__ float sC[8][EE];
    __shared__ float sL[8][EE];
    const int tid = threadIdx.x;
    const int b0 = blockIdx.y * 8;

    for (int i = tid; i < 8 * EE; i += 256) {
        int b = i >> 9, k = i & (EE - 1);
        sC[b][k] = enc_outs[((size_t)(b0 + b) * 128 + 127) * EE + k];
        sL[b][k] = embed[(size_t)src_lang[b0 + b] * EE + k];
    }
    __syncthreads();

    const int g = blockIdx.x * 256 + tid;
    const float* wr = W0 + (size_t)g * 1536;
    float acc[8];
#pragma unroll
    for (int i = 0; i < 8; i++) acc[i] = 0.0f;

    for (int k = 0; k < EE; k += 4) {
        float4 wc = *reinterpret_cast<const float4*>(wr + 512 + k);
        float4 wl = *reinterpret_cast<const float4*>(wr + 1024 + k);
#pragma unroll
        for (int b = 0; b < 8; b++) {
            float4 c4 = *reinterpret_cast<const float4*>(&sC[b][k]);
            float4 l4 = *reinterpret_cast<const float4*>(&sL[b][k]);
            acc[b] += wc.x * c4.x + wc.y * c4.y + wc.z * c4.z + wc.w * c4.w;
            acc[b] += wl.x * l4.x + wl.y * l4.y + wl.z * l4.z + wl.w * l4.w;
        }
    }
    float bias = b_ih0[g] + b_hh0[g];
#pragma unroll
    for (int b = 0; b < 8; b++) g_sp[(b0 + b) * GG + g] = acc[b] + bias;
}

// =====================================================================
// k_precompute: g_P0[t][b][g] = embed[tok[b][t]][0:512] @ W_ih_l0[g][0:512] + g_sp[b][g]
// grid (SS, GG/32): block = one timestep x 32 gate columns, 256 threads.
// thread (j = tid&31 -> column, mg = tid>>5 -> 8 batch rows)
// =====================================================================
__global__ void __launch_bounds__(256) k_precompute(
    const int* __restrict__ tokens, const float* __restrict__ embed,
    const float* __restrict__ W0) {
    __shared__ float sA[64][68];
    __shared__ int sTok[64];
    const int tid = threadIdx.x;
    const int t = blockIdx.x;
    const int col0 = blockIdx.y * 32;

    if (tid < 64) sTok[tid] = tokens[tid * SS + t];  // tok[b][t]
    __syncthreads();

    const int j = tid & 31;
    const int mg = tid >> 5;
    const int col = col0 + j;
    const float* wrow = W0 + (size_t)col * 1536;  // x-part = first 512 cols

    u64t acc[8];
#pragma unroll
    for (int i = 0; i < 8; i++) acc[i] = 0ull;

    const int row = tid >> 2, l4 = tid & 3;
#pragma unroll 1
    for (int k0 = 0; k0 < EE; k0 += 64) {
        const float* erow = embed + (size_t)sTok[row] * EE + k0;
#pragma unroll
        for (int q = 0; q < 4; q++) {
            int f = (l4 + q * 4) * 4;
            *reinterpret_cast<float4*>(&sA[row][f]) =
                *reinterpret_cast<const float4*>(erow + f);
        }
        __syncthreads();
#pragma unroll
        for (int kk = 0; kk < 64; kk += 4) {
            ulonglong2 w = *reinterpret_cast<const ulonglong2*>(wrow + k0 + kk);
#pragma unroll
            for (int mi = 0; mi < 8; mi++) {
                ulonglong2 a = *reinterpret_cast<const ulonglong2*>(&sA[mg * 8 + mi][kk]);
                fma2(acc[mi], a.x, w.x);
                fma2(acc[mi], a.y, w.y);
            }
        }
        __syncthreads();
    }
#pragma unroll
    for (int mi = 0; mi < 8; mi++) {
        int m = mg * 8 + mi;  // batch
        g_P0[((size_t)t * BB + m) * GG + col] = hsum2(acc[mi]) + g_sp[m * GG + col];
    }
}

// =====================================================================
// k_layer0: one step of LSTM layer 0 (fused GEMM + cell update).
// grid 128: block owns 8 hidden units -> 32 gate columns (i,f,g,o interleaved).
// Reads h0[rd], writes h0[wr]; c0 is owner-exclusive.
// =====================================================================
__global__ void __launch_bounds__(256) k_layer0(int t, const float* __restrict__ Whh0) {
    __shared__ float sA[64][68];
    __shared__ float sg[64][32];
    const int tid = threadIdx.x;
    const int hu0 = blockIdx.x * 8;
    const int rd = t & 1, wr = 1 - rd;

    const int j = tid & 31, mg = tid >> 5;
    const int q = j >> 3, hh = j & 7;
    const int col = q * HH + hu0 + hh;
    const float* wrow = Whh0 + (size_t)col * HH;

    u64t acc[8];
#pragma unroll
    for (int i = 0; i < 8; i++) acc[i] = 0ull;

    const int row = tid >> 2, l4 = tid & 3;
#pragma unroll 1
    for (int k0 = 0; k0 < HH; k0 += 64) {
        const float* arow = g_h0[rd] + row * HH + k0;
#pragma unroll
        for (int q4 = 0; q4 < 4; q4++) {
            int f = (l4 + q4 * 4) * 4;
            *reinterpret_cast<float4*>(&sA[row][f]) =
                *reinterpret_cast<const float4*>(arow + f);
        }
        __syncthreads();
#pragma unroll
        for (int kk = 0; kk < 64; kk += 4) {
            ulonglong2 w = *reinterpret_cast<const ulonglong2*>(wrow + k0 + kk);
#pragma unroll
            for (int mi = 0; mi < 8; mi++) {
                ulonglong2 a = *reinterpret_cast<const ulonglong2*>(&sA[mg * 8 + mi][kk]);
                fma2(acc[mi], a.x, w.x);
                fma2(acc[mi], a.y, w.y);
            }
        }
        __syncthreads();
    }

    const float* p0 = g_P0 + (size_t)t * BB * GG;
#pragma unroll
    for (int mi = 0; mi < 8; mi++) {
        int m = mg * 8 + mi;
        sg[m][j] = hsum2(acc[mi]) + p0[m * GG + col];
    }
    __syncthreads();

    // cell update: 512 cells (64 b x 8 hu), 2 per thread
    for (int c = tid; c < 512; c += 256) {
        int m = c >> 3, h2 = c & 7;
        float gi = sg[m][h2];
        float gf = sg[m][8 + h2];
        float gg = sg[m][16 + h2];
        float go = sg[m][24 + h2];
        int idx = m * HH + hu0 + h2;
        float cn = sigf(gf) * g_c0[idx] + sigf(gi) * tanhf(gg);
        g_c0[idx] = cn;
        g_h0[wr][idx] = sigf(go) * tanhf(cn);
    }
}

// =====================================================================
// k_layer1: one step of LSTM layer 1. Two GEMM phases:
//   phase 0: A = h0_new (g_h0[wr]),  W = W_ih_l1
//   phase 1: A = h1_prev (g_h1[rd]), W = W_hh_l1
// Writes h1[wr] and the output slice out[t].
// =====================================================================
__global__ void __launch_bounds__(256) k_layer1(int t, const float* __restrict__ Wih1,
                                                const float* __restrict__ Whh1,
                                                float* __restrict__ out) {
    __shared__ float sA[64][68];
    __shared__ float sg[64][32];
    const int tid = threadIdx.x;
    const int hu0 = blockIdx.x * 8;
    const int rd = t & 1, wr = 1 - rd;

    const int j = tid & 31, mg = tid >> 5;
    const int q = j >> 3, hh = j & 7;
    const int col = q * HH + hu0 + hh;

    u64t acc[8];
#pragma unroll
    for (int i = 0; i < 8; i++) acc[i] = 0ull;

    const int row = tid >> 2, l4 = tid & 3;
#pragma unroll 1
    for (int ph = 0; ph < 2; ph++) {
        const float* Abase = (ph == 0) ? g_h0[wr] : g_h1[rd];
        const float* wrow = ((ph == 0) ? Wih1 : Whh1) + (size_t)col * HH;
#pragma unroll 1
        for (int k0 = 0; k0 < HH; k0 += 64) {
            const float* arow = Abase + row * HH + k0;
#pragma unroll
            for (int q4 = 0; q4 < 4; q4++) {
                int f = (l4 + q4 * 4) * 4;
                *reinterpret_cast<float4*>(&sA[row][f]) =
                    *reinterpret_cast<const float4*>(arow + f);
            }
            __syncthreads();
#pragma unroll
            for (int kk = 0; kk < 64; kk += 4) {
                ulonglong2 w = *reinterpret_cast<const ulonglong2*>(wrow + k0 + kk);
#pragma unroll
                for (int mi = 0; mi < 8; mi++) {
                    ulonglong2 a = *reinterpret_cast<const ulonglong2*>(&sA[mg * 8 + mi][kk]);
                    fma2(acc[mi], a.x, w.x);
                    fma2(acc[mi], a.y, w.y);
                }
            }
            __syncthreads();
        }
    }

#pragma unroll
    for (int mi = 0; mi < 8; mi++) {
        int m = mg * 8 + mi;
        sg[m][j] = hsum2(acc[mi]) + g_b1[col];
    }
    __syncthreads();

    for (int c = tid; c < 512; c += 256) {
        int m = c >> 3, h2 = c & 7;
        float gi = sg[m][h2];
        float gf = sg[m][8 + h2];
        float gg = sg[m][16 + h2];
        float go = sg[m][24 + h2];
        int idx = m * HH + hu0 + h2;
        float cn = sigf(gf) * g_c1[idx] + sigf(gi) * tanhf(gg);
        g_c1[idx] = cn;
        float hn = sigf(go) * tanhf(cn);
        g_h1[wr][idx] = hn;
        out[(size_t)t * BB * HH + idx] = hn;  // outs[t][b][h]
    }
}

// =====================================================================
extern "C" void kernel_launch(void* const* d_in, const int* in_sizes, int n_in,
                              void* d_out, int out_size) {
    const int*   tok      = (const int*)d_in[0];
    const int*   src      = (const int*)d_in[1];
    const float* enc_outs = (const float*)d_in[2];
    const float* enc_h    = (const float*)d_in[3];
    const float* enc_c    = (const float*)d_in[4];
    const float* embed    = (const float*)d_in[5];
    const float* W_ih0    = (const float*)d_in[6];
    const float* W_hh0    = (const float*)d_in[7];
    const float* b_ih0    = (const float*)d_in[8];
    const float* b_hh0    = (const float*)d_in[9];
    const float* W_ih1    = (const float*)d_in[10];
    const float* W_hh1    = (const float*)d_in[11];
    const float* b_ih1    = (const float*)d_in[12];
    const float* b_hh1    = (const float*)d_in[13];
    float* out = (float*)d_out;

    k_init<<<(BB * HH + 255) / 256, 256>>>(enc_h, enc_c, b_ih1, b_hh1);
    k_static<<<dim3(GG / 256, BB / 8), 256>>>(enc_outs, src, embed, W_ih0, b_ih0, b_hh0);
    k_precompute<<<dim3(SS, GG / 32), 256>>>(tok, embed, W_ih0);

    for (int t = 0; t < SS; t++) {
        k_layer0<<<HH / 8, 256>>>(t, W_hh0);
        k_layer1<<<HH / 8, 256>>>(t, W_ih1, W_hh1, out);
    }
}

// round 5
// speedup vs baseline: 2.0409x; 2.0409x over previous
#include <cuda_runtime.h>
#include <cuda_bf16.h>
#include <math.h>

// Problem constants
#define BB 64
#define SS 256
#define HH 1024
#define EE 512
#define GG 4096   // 4*H

// -------- scratch (device globals: sanctioned, no allocations) --------
__device__ float g_P0[(size_t)SS * BB * GG];  // precomputed input-side gates
__device__ float g_sp[BB * GG];               // static-part gates (time-invariant)
__device__ float g_b1[GG];                    // b_ih_l1 + b_hh_l1
__device__ float g_h0[2][BB * HH];            // double-buffered recurrent h (layer 0)
__device__ float g_h1[2][BB * HH];            // double-buffered recurrent h (layer 1)
__device__ float g_c0[BB * HH];               // cell states (owner-only access)
__device__ float g_c1[BB * HH];

// -------- packed fp32x2 FMA helpers --------
typedef unsigned long long u64t;

__device__ __forceinline__ void fma2(u64t& c, u64t a, u64t b) {
    asm("fma.rn.f32x2 %0, %1, %2, %0;" : "+l"(c) : "l"(a), "l"(b));
}
__device__ __forceinline__ float hsum2(u64t v) {
    return __uint_as_float((unsigned)(v & 0xffffffffu)) +
           __uint_as_float((unsigned)(v >> 32));
}
__device__ __forceinline__ float sigf(float x) { return 1.0f / (1.0f + expf(-x)); }

// =====================================================================
// k_init
// =====================================================================
__global__ void k_init(const float* __restrict__ enc_h, const float* __restrict__ enc_c,
                       const float* __restrict__ b_ih1, const float* __restrict__ b_hh1) {
    int i = blockIdx.x * blockDim.x + threadIdx.x;
    const int n = BB * HH;
    if (i < n) {
        g_h0[0][i] = enc_h[i];
        g_c0[i]    = enc_c[i];
        g_h1[0][i] = enc_h[n + i];
        g_c1[i]    = enc_c[n + i];
    }
    if (i < GG) g_b1[i] = b_ih1[i] + b_hh1[i];
}

// =====================================================================
// k_static: one-time static-part gates (small; unchanged from R4)
// =====================================================================
__global__ void __launch_bounds__(256) k_static(
    const float* __restrict__ enc_outs, const int* __restrict__ src_lang,
    const float* __restrict__ embed, const float* __restrict__ W0,
    const float* __restrict__ b_ih0, const float* __restrict__ b_hh0) {
    __shared__ float sC[8][EE];
    __shared__ float sL[8][EE];
    const int tid = threadIdx.x;
    const int b0 = blockIdx.y * 8;

    for (int i = tid; i < 8 * EE; i += 256) {
        int b = i >> 9, k = i & (EE - 1);
        sC[b][k] = enc_outs[((size_t)(b0 + b) * 128 + 127) * EE + k];
        sL[b][k] = embed[(size_t)src_lang[b0 + b] * EE + k];
    }
    __syncthreads();

    const int g = blockIdx.x * 256 + tid;
    const float* wr = W0 + (size_t)g * 1536;
    float acc[8];
#pragma unroll
    for (int i = 0; i < 8; i++) acc[i] = 0.0f;

    for (int k = 0; k < EE; k += 4) {
        float4 wc = *reinterpret_cast<const float4*>(wr + 512 + k);
        float4 wl = *reinterpret_cast<const float4*>(wr + 1024 + k);
#pragma unroll
        for (int b = 0; b < 8; b++) {
            float4 c4 = *reinterpret_cast<const float4*>(&sC[b][k]);
            float4 l4 = *reinterpret_cast<const float4*>(&sL[b][k]);
            acc[b] += wc.x * c4.x + wc.y * c4.y + wc.z * c4.z + wc.w * c4.w;
            acc[b] += wl.x * l4.x + wl.y * l4.y + wl.z * l4.z + wl.w * l4.w;
        }
    }
    float bias = b_ih0[g] + b_hh0[g];
#pragma unroll
    for (int b = 0; b < 8; b++) g_sp[(b0 + b) * GG + g] = acc[b] + bias;
}

// =====================================================================
// k_precompute: P0[t][b][g] = embed[tok[b][t]][:512] @ W_ih0[g][:512] + sp[b][g]
// W now staged via smem (coalesced) with register double-buffering.
// grid (SS, GG/32), 256 threads.
// =====================================================================
__global__ void __launch_bounds__(256) k_precompute(
    const int* __restrict__ tokens, const float* __restrict__ embed,
    const float* __restrict__ W0) {
    __shared__ __align__(16) float sA[64][68];
    __shared__ __align__(16) float sW[32][68];
    __shared__ int sTok[64];
    const int tid = threadIdx.x;
    const int t = blockIdx.x;
    const int col0 = blockIdx.y * 32;

    const int j = tid & 31, mg = tid >> 5;

    // A-load mapping: row = tid>>2, 4 float4 per thread
    const int ar = tid >> 2, al = tid & 3;
    // W-load mapping: row = tid>>3, 8 contiguous floats at (tid&7)*8
    const int wri = tid >> 3, wci = (tid & 7) * 8;
    const float* wgrow = W0 + (size_t)(col0 + wri) * 1536 + wci;

    if (tid < 64) sTok[tid] = tokens[tid * SS + t];
    __syncthreads();
    const float* arow = embed + (size_t)sTok[ar] * EE;

    u64t acc[8];
#pragma unroll
    for (int i = 0; i < 8; i++) acc[i] = 0ull;

    float4 pA[4], pW[2];
    // prefetch chunk 0
#pragma unroll
    for (int q = 0; q < 4; q++)
        pA[q] = *reinterpret_cast<const float4*>(arow + (al + 4 * q) * 4);
    pW[0] = *reinterpret_cast<const float4*>(wgrow);
    pW[1] = *reinterpret_cast<const float4*>(wgrow + 4);

#pragma unroll 1
    for (int c = 0; c < EE / 64; c++) {
#pragma unroll
        for (int q = 0; q < 4; q++)
            *reinterpret_cast<float4*>(&sA[ar][(al + 4 * q) * 4]) = pA[q];
        *reinterpret_cast<float4*>(&sW[wri][wci]) = pW[0];
        *reinterpret_cast<float4*>(&sW[wri][wci + 4]) = pW[1];
        __syncthreads();

        if (c + 1 < EE / 64) {
            int k1 = (c + 1) * 64;
#pragma unroll
            for (int q = 0; q < 4; q++)
                pA[q] = *reinterpret_cast<const float4*>(arow + k1 + (al + 4 * q) * 4);
            pW[0] = *reinterpret_cast<const float4*>(wgrow + k1);
            pW[1] = *reinterpret_cast<const float4*>(wgrow + k1 + 4);
        }

#pragma unroll
        for (int kk = 0; kk < 64; kk += 4) {
            ulonglong2 w = *reinterpret_cast<const ulonglong2*>(&sW[j][kk]);
#pragma unroll
            for (int mi = 0; mi < 8; mi++) {
                ulonglong2 a = *reinterpret_cast<const ulonglong2*>(&sA[mg * 8 + mi][kk]);
                fma2(acc[mi], a.x, w.x);
                fma2(acc[mi], a.y, w.y);
            }
        }
        __syncthreads();
    }

    const int col = col0 + j;
#pragma unroll
    for (int mi = 0; mi < 8; mi++) {
        int m = mg * 8 + mi;
        g_P0[((size_t)t * BB + m) * GG + col] = hsum2(acc[mi]) + g_sp[m * GG + col];
    }
}

// =====================================================================
// k_layer0: one step of LSTM layer 0, W via smem + reg double-buffer.
// grid 128, 256 threads. Block owns 8 hidden units (32 gate cols).
// =====================================================================
__global__ void __launch_bounds__(256) k_layer0(int t, const float* __restrict__ W) {
    __shared__ __align__(16) float sA[64][68];
    __shared__ __align__(16) float sW[32][68];
    __shared__ float sg[64][32];
    const int tid = threadIdx.x;
    const int hu0 = blockIdx.x * 8;
    const int rd = t & 1, wrb = 1 - rd;

    const int j = tid & 31, mg = tid >> 5;

    const int ar = tid >> 2, al = tid & 3;
    const int wri = tid >> 3, wci = (tid & 7) * 8;
    // gate-col for W row wri (same (q,hh) encoding as j)
    const int gcol_w = (wri >> 3) * HH + hu0 + (wri & 7);
    const float* wgrow = W + (size_t)gcol_w * HH + wci;
    const float* arow = g_h0[rd] + ar * HH;

    u64t acc[8];
#pragma unroll
    for (int i = 0; i < 8; i++) acc[i] = 0ull;

    float4 pA[4], pW[2];
#pragma unroll
    for (int q = 0; q < 4; q++)
        pA[q] = *reinterpret_cast<const float4*>(arow + (al + 4 * q) * 4);
    pW[0] = *reinterpret_cast<const float4*>(wgrow);
    pW[1] = *reinterpret_cast<const float4*>(wgrow + 4);

#pragma unroll 1
    for (int c = 0; c < HH / 64; c++) {
#pragma unroll
        for (int q = 0; q < 4; q++)
            *reinterpret_cast<float4*>(&sA[ar][(al + 4 * q) * 4]) = pA[q];
        *reinterpret_cast<float4*>(&sW[wri][wci]) = pW[0];
        *reinterpret_cast<float4*>(&sW[wri][wci + 4]) = pW[1];
        __syncthreads();

        if (c + 1 < HH / 64) {
            int k1 = (c + 1) * 64;
#pragma unroll
            for (int q = 0; q < 4; q++)
                pA[q] = *reinterpret_cast<const float4*>(arow + k1 + (al + 4 * q) * 4);
            pW[0] = *reinterpret_cast<const float4*>(wgrow + k1);
            pW[1] = *reinterpret_cast<const float4*>(wgrow + k1 + 4);
        }

#pragma unroll
        for (int kk = 0; kk < 64; kk += 4) {
            ulonglong2 w = *reinterpret_cast<const ulonglong2*>(&sW[j][kk]);
#pragma unroll
            for (int mi = 0; mi < 8; mi++) {
                ulonglong2 a = *reinterpret_cast<const ulonglong2*>(&sA[mg * 8 + mi][kk]);
                fma2(acc[mi], a.x, w.x);
                fma2(acc[mi], a.y, w.y);
            }
        }
        __syncthreads();
    }

    const int q = j >> 3, hh = j & 7;
    const int col = q * HH + hu0 + hh;
    const float* p0 = g_P0 + (size_t)t * BB * GG;
#pragma unroll
    for (int mi = 0; mi < 8; mi++) {
        int m = mg * 8 + mi;
        sg[m][j] = hsum2(acc[mi]) + p0[m * GG + col];
    }
    __syncthreads();

    for (int cc = tid; cc < 512; cc += 256) {
        int m = cc >> 3, h2 = cc & 7;
        float gi = sg[m][h2];
        float gf = sg[m][8 + h2];
        float gg = sg[m][16 + h2];
        float go = sg[m][24 + h2];
        int idx = m * HH + hu0 + h2;
        float cn = sigf(gf) * g_c0[idx] + sigf(gi) * tanhf(gg);
        g_c0[idx] = cn;
        g_h0[wrb][idx] = sigf(go) * tanhf(cn);
    }
}

// =====================================================================
// k_layer1: one step of layer 1. Two GEMM phases (h0_new@Wih1, h1_prev@Whh1),
// 32 chunks total, same smem staging + prefetch.
// =====================================================================
__global__ void __launch_bounds__(256) k_layer1(int t, const float* __restrict__ Wih1,
                                                const float* __restrict__ Whh1,
                                                float* __restrict__ out) {
    __shared__ __align__(16) float sA[64][68];
    __shared__ __align__(16) float sW[32][68];
    __shared__ float sg[64][32];
    const int tid = threadIdx.x;
    const int hu0 = blockIdx.x * 8;
    const int rd = t & 1, wrb = 1 - rd;

    const int j = tid & 31, mg = tid >> 5;

    const int ar = tid >> 2, al = tid & 3;
    const int wri = tid >> 3, wci = (tid & 7) * 8;
    const int gcol_w = (wri >> 3) * HH + hu0 + (wri & 7);
    const size_t woff = (size_t)gcol_w * HH + wci;

    const float* Ab[2] = { g_h0[wrb], g_h1[rd] };
    const float* Wb[2] = { Wih1 + woff, Whh1 + woff };

    u64t acc[8];
#pragma unroll
    for (int i = 0; i < 8; i++) acc[i] = 0ull;

    float4 pA[4], pW[2];
    {
        const float* arow = Ab[0] + ar * HH;
#pragma unroll
        for (int q = 0; q < 4; q++)
            pA[q] = *reinterpret_cast<const float4*>(arow + (al + 4 * q) * 4);
        pW[0] = *reinterpret_cast<const float4*>(Wb[0]);
        pW[1] = *reinterpret_cast<const float4*>(Wb[0] + 4);
    }

#pragma unroll 1
    for (int c = 0; c < 32; c++) {
#pragma unroll
        for (int q = 0; q < 4; q++)
            *reinterpret_cast<float4*>(&sA[ar][(al + 4 * q) * 4]) = pA[q];
        *reinterpret_cast<float4*>(&sW[wri][wci]) = pW[0];
        *reinterpret_cast<float4*>(&sW[wri][wci + 4]) = pW[1];
        __syncthreads();

        if (c + 1 < 32) {
            int cn = c + 1;
            int ph = cn >> 4;
            int k1 = (cn & 15) * 64;
            const float* arow = Ab[ph] + ar * HH + k1;
#pragma unroll
            for (int q = 0; q < 4; q++)
                pA[q] = *reinterpret_cast<const float4*>(arow + (al + 4 * q) * 4);
            pW[0] = *reinterpret_cast<const float4*>(Wb[ph] + k1);
            pW[1] = *reinterpret_cast<const float4*>(Wb[ph] + k1 + 4);
        }

#pragma unroll
        for (int kk = 0; kk < 64; kk += 4) {
            ulonglong2 w = *reinterpret_cast<const ulonglong2*>(&sW[j][kk]);
#pragma unroll
            for (int mi = 0; mi < 8; mi++) {
                ulonglong2 a = *reinterpret_cast<const ulonglong2*>(&sA[mg * 8 + mi][kk]);
                fma2(acc[mi], a.x, w.x);
                fma2(acc[mi], a.y, w.y);
            }
        }
        __syncthreads();
    }

    const int q = j >> 3, hh = j & 7;
    const int col = q * HH + hu0 + hh;
#pragma unroll
    for (int mi = 0; mi < 8; mi++) {
        int m = mg * 8 + mi;
        sg[m][j] = hsum2(acc[mi]) + g_b1[col];
    }
    __syncthreads();

    for (int cc = tid; cc < 512; cc += 256) {
        int m = cc >> 3, h2 = cc & 7;
        float gi = sg[m][h2];
        float gf = sg[m][8 + h2];
        float gg = sg[m][16 + h2];
        float go = sg[m][24 + h2];
        int idx = m * HH + hu0 + h2;
        float cn = sigf(gf) * g_c1[idx] + sigf(gi) * tanhf(gg);
        g_c1[idx] = cn;
        float hn = sigf(go) * tanhf(cn);
        g_h1[wrb][idx] = hn;
        out[(size_t)t * BB * HH + idx] = hn;
    }
}

// =====================================================================
extern "C" void kernel_launch(void* const* d_in, const int* in_sizes, int n_in,
                              void* d_out, int out_size) {
    const int*   tok      = (const int*)d_in[0];
    const int*   src      = (const int*)d_in[1];
    const float* enc_outs = (const float*)d_in[2];
    const float* enc_h    = (const float*)d_in[3];
    const float* enc_c    = (const float*)d_in[4];
    const float* embed    = (const float*)d_in[5];
    const float* W_ih0    = (const float*)d_in[6];
    const float* W_hh0    = (const float*)d_in[7];
    const float* b_ih0    = (const float*)d_in[8];
    const float* b_hh0    = (const float*)d_in[9];
    const float* W_ih1    = (const float*)d_in[10];
    const float* W_hh1    = (const float*)d_in[11];
    const float* b_ih1    = (const float*)d_in[12];
    const float* b_hh1    = (const float*)d_in[13];
    float* out = (float*)d_out;

    k_init<<<(BB * HH + 255) / 256, 256>>>(enc_h, enc_c, b_ih1, b_hh1);
    k_static<<<dim3(GG / 256, BB / 8), 256>>>(enc_outs, src, embed, W_ih0, b_ih0, b_hh0);
    k_precompute<<<dim3(SS, GG / 32), 256>>>(tok, embed, W_ih0);

    for (int t = 0; t < SS; t++) {
        k_layer0<<<HH / 8, 256>>>(t, W_hh0);
        k_layer1<<<HH / 8, 256>>>(t, W_ih1, W_hh1, out);
    }
}